// round 7
// baseline (speedup 1.0000x reference)
#include <cuda_runtime.h>
#include <cstdint>
#include <cstddef>

#define T_TOKENS 4096
#define DM 2048
#define DH 1408
#define NE 32
#define NS 2
#define TOPK 6
#define NPASS 34
#define RPAIRS (T_TOKENS * TOPK)          /* 24576 routed pairs */
#define NSLOTS (RPAIRS + NS * T_TOKENS)   /* 32768 total slots  */

#define BM 128
#define BN 128
#define BK 32
#define SMEM_DYN 99328                     /* 3 stages x 32KB + align slack */

// ---------------- scratch (static device globals; no allocations) -----------
__device__ uint32_t g_X[(size_t)T_TOKENS * DM];          // x as tf32 bits
__device__ uint32_t g_H[(size_t)NSLOTS * DH];            // hidden acts, tf32 bits
__device__ float    g_O[(size_t)NSLOTS * DM];            // per-slot outputs
__device__ uint32_t g_WT1[(size_t)NPASS * DM * DH];      // W1^T [e][n=DH][k=DM] tf32
__device__ uint32_t g_WT2[(size_t)NPASS * DH * DM];      // W2^T [e][n=DM][k=DH] tf32
__device__ float g_gates[T_TOKENS * NE];
__device__ int   g_tok[RPAIRS];
__device__ float g_gate[RPAIRS];
__device__ int   g_slotof[T_TOKENS * TOPK];
__device__ int   g_cnt[NE];
__device__ int   g_off[NE];
__device__ int   g_cur[NE];
__device__ int   g_tcnt[T_TOKENS];
__device__ int   g_passcnt[NPASS];
__device__ int   g_done;

// ---------------- PTX helpers (plain sm_80+ features only) ------------------
__device__ __forceinline__ uint32_t f2tf32(float x) {
    uint32_t r;
    asm("cvt.rna.tf32.f32 %0, %1;" : "=r"(r) : "f"(x));
    return r;
}
__device__ __forceinline__ uint32_t smem_u32(const void* p) {
    uint32_t r;
    asm("{ .reg .u64 t; cvta.to.shared.u64 t, %1; cvt.u32.u64 %0, t; }"
        : "=r"(r) : "l"(p));
    return r;
}
__device__ __forceinline__ void cpa16(uint32_t dst, const void* src) {
    asm volatile("cp.async.cg.shared.global [%0], [%1], 16;"
                 :: "r"(dst), "l"(src) : "memory");
}
__device__ __forceinline__ void cpa_commit() {
    asm volatile("cp.async.commit_group;" ::: "memory");
}
template <int N>
__device__ __forceinline__ void cpa_wait() {
    asm volatile("cp.async.wait_group %0;" :: "n"(N) : "memory");
}
__device__ __forceinline__ void mma_tf32(float* d, const uint32_t* a,
                                         uint32_t b0, uint32_t b1) {
    asm("mma.sync.aligned.m16n8k8.row.col.f32.tf32.tf32.f32 "
        "{%0,%1,%2,%3}, {%4,%5,%6,%7}, {%8,%9}, {%0,%1,%2,%3};"
        : "+f"(d[0]), "+f"(d[1]), "+f"(d[2]), "+f"(d[3])
        : "r"(a[0]), "r"(a[1]), "r"(a[2]), "r"(a[3]), "r"(b0), "r"(b1));
}

// swizzled 16B-chunk byte offset within a 128-row x 128B tile
__device__ __forceinline__ uint32_t sw16(uint32_t row, uint32_t chunk) {
    return row * 128u + ((chunk ^ (row & 7u)) << 4);
}
// swizzled u32-word index for element (row, k) — k in 0..31
__device__ __forceinline__ uint32_t widx(uint32_t row, uint32_t k) {
    return row * 32u + (((k >> 2) ^ (row & 7u)) << 2) + (k & 3u);
}

// ---------------- prep: weight transposes + x conversion + zeroing ----------
// grid layout (1D):
//   [0, NT1)            : WT1 transpose tiles (e, kt, nt)
//   [NT1, NT1+NT2)      : WT2 transpose tiles
//   [.., +XB)           : x -> tf32 conversion
//   [.., +ZB)           : zero g_tcnt / g_cnt / g_done
#define NT1 (NPASS * (DM / 32) * (DH / 32))
#define NT2 (NPASS * (DH / 32) * (DM / 32))
#define XB  ((T_TOKENS * DM) / (256 * 4))
#define ZB  (T_TOKENS / 256 + 1)

__global__ void prep_kernel(const float* __restrict__ x,
                            const float* __restrict__ rw1, const float* __restrict__ sw1,
                            const float* __restrict__ rw2, const float* __restrict__ sw2) {
    __shared__ float tile[32][33];
    const int b   = blockIdx.x;
    const int tid = threadIdx.x;
    const int tx  = tid & 31, ty = tid >> 5;

    if (b < NT1 + NT2) {
        const bool w2 = (b >= NT1);
        const int  bb = w2 ? (b - NT1) : b;
        const int  K  = w2 ? DH : DM;
        const int  N  = w2 ? DM : DH;
        const int  ntiles = N / 32;
        const int  e  = bb / ((K / 32) * ntiles);
        const int  rm = bb % ((K / 32) * ntiles);
        const int  kt = rm / ntiles, nt = rm % ntiles;
        const float* R = w2 ? rw2 : rw1;
        const float* S = w2 ? sw2 : sw1;
        const float* src = (e < NE) ? (R + (size_t)e * K * N)
                                    : (S + (size_t)(e - NE) * K * N);
        uint32_t* dst = (w2 ? g_WT2 : g_WT1) + (size_t)e * (size_t)K * N;
        const int n0 = nt * 32, k0 = kt * 32;
        #pragma unroll
        for (int i = ty; i < 32; i += 8)
            tile[i][tx] = src[(size_t)(k0 + i) * N + n0 + tx];
        __syncthreads();
        #pragma unroll
        for (int i = ty; i < 32; i += 8)
            dst[(size_t)(n0 + i) * K + k0 + tx] = f2tf32(tile[tx][i]);
    } else if (b < NT1 + NT2 + XB) {
        size_t i = ((size_t)(b - NT1 - NT2) * 256 + tid) * 4;
        float4 v = *reinterpret_cast<const float4*>(x + i);
        uint4 o;
        o.x = f2tf32(v.x); o.y = f2tf32(v.y); o.z = f2tf32(v.z); o.w = f2tf32(v.w);
        *reinterpret_cast<uint4*>(g_X + i) = o;
    } else {
        const int zb = b - NT1 - NT2 - XB;
        if (zb < T_TOKENS / 256) {
            g_tcnt[zb * 256 + tid] = 0;
        } else {
            if (tid < NE) g_cnt[tid] = 0;
            if (tid == NE) g_done = 0;
        }
    }
}

// ---------------- router (+ tail-block expert scan) --------------------------
__global__ void router_kernel(const float* __restrict__ x,
                              const float* __restrict__ rw,
                              const float* __restrict__ rb) {
    const int gw   = (blockIdx.x * blockDim.x + threadIdx.x) >> 5;
    const int lane = threadIdx.x & 31;
    // grid sized exactly: every thread has a token
    {
        const float* xr = x + (size_t)gw * DM;
        float acc = __ldg(rb + lane);
        for (int k = 0; k < DM; k += 4) {
            float4 xv = *reinterpret_cast<const float4*>(xr + k);
            acc = fmaf(xv.x, __ldg(rw + (k + 0) * NE + lane), acc);
            acc = fmaf(xv.y, __ldg(rw + (k + 1) * NE + lane), acc);
            acc = fmaf(xv.z, __ldg(rw + (k + 2) * NE + lane), acc);
            acc = fmaf(xv.w, __ldg(rw + (k + 3) * NE + lane), acc);
        }
        float m = acc;
        for (int o = 16; o; o >>= 1) m = fmaxf(m, __shfl_xor_sync(0xffffffffu, m, o));
        float e = expf(acc - m);
        float s = e;
        for (int o = 16; o; o >>= 1) s += __shfl_xor_sync(0xffffffffu, s, o);
        float p = e / s;
        float pv = p, sum6 = 0.0f;
        bool sel = false;
        #pragma unroll
        for (int j = 0; j < TOPK; j++) {
            float v = pv; int idx = lane;
            for (int o = 16; o; o >>= 1) {
                float ov = __shfl_xor_sync(0xffffffffu, v, o);
                int   oi = __shfl_xor_sync(0xffffffffu, idx, o);
                if (ov > v || (ov == v && oi < idx)) { v = ov; idx = oi; }
            }
            sum6 += v;
            if (lane == idx) { pv = -1.0f; sel = true; }
        }
        float gate = sel ? (p / sum6) : 0.0f;
        g_gates[gw * NE + lane] = gate;
        if (sel) atomicAdd(&g_cnt[lane], 1);
    }
    // last-block scan (replaces separate scan_kernel launch)
    __shared__ int s_last;
    __syncthreads();
    if (threadIdx.x == 0) {
        __threadfence();
        s_last = (atomicAdd(&g_done, 1) == (int)gridDim.x - 1) ? 1 : 0;
    }
    __syncthreads();
    if (s_last && threadIdx.x < 32) {
        const int ln = threadIdx.x;
        int c = (ln < NE) ? g_cnt[ln] : 0;
        int s = c;
        for (int o = 1; o < 32; o <<= 1) {
            int v = __shfl_up_sync(0xffffffffu, s, o);
            if (ln >= o) s += v;
        }
        if (ln < NE) { g_off[ln] = s - c; g_cur[ln] = 0; g_passcnt[ln] = c; }
        if (ln < NS) g_passcnt[NE + ln] = T_TOKENS;
    }
}

__global__ void pairs_kernel() {
    int idx = blockIdx.x * blockDim.x + threadIdx.x;
    if (idx >= T_TOKENS * NE) return;
    int t = idx >> 5, e = idx & 31;
    float gate = g_gates[idx];
    if (gate > 0.0f) {
        int pos  = atomicAdd(&g_cur[e], 1);
        int slot = g_off[e] + pos;
        g_tok[slot]  = t;
        g_gate[slot] = gate;
        int j = atomicAdd(&g_tcnt[t], 1);
        g_slotof[t * TOPK + j] = slot;
    }
}

// ---------------- expert GEMM: mma.sync tf32, 3-stage cp.async ---------------
// MODE 0: g_H = tf32(relu(gather(g_X) @ W1 + b1))   K=DM, N=DH
// MODE 1: g_O[slot] = gate * (g_H @ W2 + b2)        K=DH, N=DM
template <int MODE>
__global__ __launch_bounds__(256, 2)
void moe_gemm_tc(const float* __restrict__ RB, const float* __restrict__ SB) {
    constexpr int K   = MODE ? DH : DM;
    constexpr int N   = MODE ? DM : DH;
    constexpr int NIT = K / BK;

    const int p   = blockIdx.z;
    const int cnt = g_passcnt[p];
    const int m0  = blockIdx.y * BM;
    if (m0 >= cnt) return;
    const int n0  = blockIdx.x * BN;

    const bool routed = (p < NE);
    const int  base   = routed ? g_off[p] : (RPAIRS + (p - NE) * T_TOKENS);
    const uint32_t* WT = (MODE ? g_WT2 : g_WT1) + (size_t)p * (size_t)K * N;
    const float*    Bv = routed ? (RB + (size_t)p * N) : (SB + (size_t)(p - NE) * N);

    extern __shared__ uint8_t dsm[];
    __shared__ float s_bias[BN];

    const int tid  = threadIdx.x;
    const int wid  = tid >> 5;
    const int lane = tid & 31;

    if (tid < BN) s_bias[tid] = __ldg(Bv + n0 + tid);

    // loader coords: thread -> row r (0..127), 4 chunks of 16B at cb..cb+3
    const int r  = tid & 127;
    const int cb = (tid >> 7) * 4;
    const uint32_t* srcA;
    if (MODE == 0) {
        int i   = m0 + r;
        int tok = routed ? g_tok[base + (i < cnt ? i : cnt - 1)] : i;
        srcA = g_X + (size_t)tok * DM;
    } else {
        srcA = g_H + (size_t)(base + m0 + r) * DH;
    }
    const uint32_t* srcB = WT + (size_t)(n0 + r) * K;

    // warp / fragment coords
    const int wm = (wid & 3) * 32;
    const int wn = (wid >> 2) * 64;
    const int fg = lane >> 2;
    const int ft = lane & 3;

    // stage layout: A(16KB) + B(16KB), XOR-swizzled, 3 stages
    const uint32_t sbase = smem_u32(dsm);
    uint32_t* Sm = reinterpret_cast<uint32_t*>(dsm);

    float acc[2][8][4];
    #pragma unroll
    for (int a = 0; a < 2; a++)
        #pragma unroll
        for (int b = 0; b < 8; b++)
            #pragma unroll
            for (int c = 0; c < 4; c++) acc[a][b][c] = 0.0f;

    auto do_copy = [&](int it, int buf) {
        const int kt = it * BK;
        const uint32_t abase = sbase + (uint32_t)buf * 32768u;
        const uint32_t bbase = abase + 16384u;
        #pragma unroll
        for (int c = 0; c < 4; c++)
            cpa16(abase + sw16(r, cb + c), srcA + kt + (cb + c) * 4);
        #pragma unroll
        for (int c = 0; c < 4; c++)
            cpa16(bbase + sw16(r, cb + c), srcB + kt + (cb + c) * 4);
        cpa_commit();
    };

    do_copy(0, 0);
    do_copy(1, 1);

    #pragma unroll 1
    for (int it = 0; it < NIT; ++it) {
        const int buf = it % 3;
        if (it + 1 < NIT) cpa_wait<1>(); else cpa_wait<0>();
        __syncthreads();                 // single barrier per k-iter
        if (it + 2 < NIT) do_copy(it + 2, (it + 2) % 3);

        const uint32_t* As = Sm + (size_t)buf * 8192;    // 32KB/4
        const uint32_t* Bs = As + 4096;                  // +16KB/4
        #pragma unroll
        for (int kk = 0; kk < 4; kk++) {
            const int k0 = kk * 8 + ft;
            const int k1 = k0 + 4;
            uint32_t af[2][4];
            #pragma unroll
            for (int mi = 0; mi < 2; mi++) {
                const int rr = wm + mi * 16 + fg;
                af[mi][0] = As[widx(rr,     k0)];
                af[mi][1] = As[widx(rr + 8, k0)];
                af[mi][2] = As[widx(rr,     k1)];
                af[mi][3] = As[widx(rr + 8, k1)];
            }
            #pragma unroll
            for (int nj = 0; nj < 8; nj++) {
                const int c = wn + nj * 8 + fg;
                uint32_t b0 = Bs[widx(c, k0)];
                uint32_t b1 = Bs[widx(c, k1)];
                mma_tf32(acc[0][nj], af[0], b0, b1);
                mma_tf32(acc[1][nj], af[1], b0, b1);
            }
        }
    }

    // ---- epilogue
    #pragma unroll
    for (int mi = 0; mi < 2; mi++) {
        #pragma unroll
        for (int h = 0; h < 2; h++) {
            const int i = m0 + wm + mi * 16 + fg + h * 8;
            if (i >= cnt) continue;
            if (MODE == 0) {
                uint32_t* dst = g_H + (size_t)(base + i) * DH + n0;
                #pragma unroll
                for (int nj = 0; nj < 8; nj++) {
                    const int col = wn + nj * 8 + 2 * ft;
                    uint2 o;
                    o.x = f2tf32(fmaxf(acc[mi][nj][h * 2 + 0] + s_bias[col], 0.f));
                    o.y = f2tf32(fmaxf(acc[mi][nj][h * 2 + 1] + s_bias[col + 1], 0.f));
                    *reinterpret_cast<uint2*>(dst + col) = o;
                }
            } else {
                const float gate = routed ? g_gate[base + i] : (1.0f / NS);
                float* dst = g_O + (size_t)(base + i) * DM + n0;
                #pragma unroll
                for (int nj = 0; nj < 8; nj++) {
                    const int col = wn + nj * 8 + 2 * ft;
                    float2 o;
                    o.x = gate * (acc[mi][nj][h * 2 + 0] + s_bias[col]);
                    o.y = gate * (acc[mi][nj][h * 2 + 1] + s_bias[col + 1]);
                    *reinterpret_cast<float2*>(dst + col) = o;
                }
            }
        }
    }
}

// ---------------- final combine ------------------------------------------------
__global__ void combine_kernel(float* __restrict__ out) {
    const int t = blockIdx.x;
    const int c = threadIdx.x * 4;
    float4 acc = make_float4(0.f, 0.f, 0.f, 0.f);
    #pragma unroll
    for (int j = 0; j < TOPK; j++) {
        int slot = g_slotof[t * TOPK + j];
        float4 v = *reinterpret_cast<const float4*>(g_O + (size_t)slot * DM + c);
        acc.x += v.x; acc.y += v.y; acc.z += v.z; acc.w += v.w;
    }
    #pragma unroll
    for (int s = 0; s < NS; s++) {
        int slot = RPAIRS + s * T_TOKENS + t;
        float4 v = *reinterpret_cast<const float4*>(g_O + (size_t)slot * DM + c);
        acc.x += v.x; acc.y += v.y; acc.z += v.z; acc.w += v.w;
    }
    *reinterpret_cast<float4*>(out + (size_t)t * DM + c) = acc;
}

// ---------------- launch --------------------------------------------------------
extern "C" void kernel_launch(void* const* d_in, const int* in_sizes, int n_in,
                              void* d_out, int out_size) {
    const float* x        = (const float*)d_in[0];
    const float* sw1      = (const float*)d_in[1];
    const float* sb1      = (const float*)d_in[2];
    const float* sw2      = (const float*)d_in[3];
    const float* sb2      = (const float*)d_in[4];
    const float* rw1      = (const float*)d_in[5];
    const float* rb1      = (const float*)d_in[6];
    const float* rw2      = (const float*)d_in[7];
    const float* rb2      = (const float*)d_in[8];
    const float* router_w = (const float*)d_in[9];
    const float* router_b = (const float*)d_in[10];
    float* out = (float*)d_out;

    cudaFuncSetAttribute(moe_gemm_tc<0>, cudaFuncAttributeMaxDynamicSharedMemorySize, SMEM_DYN);
    cudaFuncSetAttribute(moe_gemm_tc<1>, cudaFuncAttributeMaxDynamicSharedMemorySize, SMEM_DYN);

    // launch 1: prep (transposes + x conversion + zeroing)
    prep_kernel<<<NT1 + NT2 + XB + ZB, 256>>>(x, rw1, sw1, rw2, sw2);
    // launch 2: router + fused expert scan
    router_kernel<<<(T_TOKENS * 32) / 256, 256>>>(x, router_w, router_b);
    // launch 3: pair lists
    pairs_kernel<<<(T_TOKENS * NE) / 256, 256>>>();

    // launch 4: GEMM1 (ncu profiles the 4th launch)
    dim3 g1(DH / BN, T_TOKENS / BM, NPASS);   // (11, 32, 34)
    moe_gemm_tc<0><<<g1, 256, SMEM_DYN>>>(rb1, sb1);

    // launch 5: GEMM2
    dim3 g2(DM / BN, T_TOKENS / BM, NPASS);   // (16, 32, 34)
    moe_gemm_tc<1><<<g2, 256, SMEM_DYN>>>(rb2, sb2);

    // launch 6: combine
    combine_kernel<<<T_TOKENS, 512>>>(out);
}

// round 8
// speedup vs baseline: 1.1639x; 1.1639x over previous
#include <cuda_runtime.h>
#include <cstdint>
#include <cstddef>

#define T_TOKENS 4096
#define DM 2048
#define DH 1408
#define NE 32
#define NS 2
#define TOPK 6
#define NPASS 34
#define RPAIRS (T_TOKENS * TOPK)          /* 24576 routed pairs */
#define NSLOTS (RPAIRS + NS * T_TOKENS)   /* 32768 total slots  */

#define BM 128
#define BN 128
#define BK 32
#define RS 36                              /* padded row stride (u32 words) */
#define SMEM_DYN 73728                     /* 2 stages x (A+B) x 128 x 36 x 4 */

// ---------------- scratch (static device globals; no allocations) -----------
__device__ uint32_t g_X[(size_t)T_TOKENS * DM];          // x as tf32 bits
__device__ uint32_t g_H[(size_t)NSLOTS * DH];            // hidden acts, tf32 bits
__device__ float    g_O[(size_t)NSLOTS * DM];            // per-slot outputs
__device__ uint32_t g_WT1[(size_t)NPASS * DM * DH];      // W1^T [e][n=DH][k=DM] tf32
__device__ uint32_t g_WT2[(size_t)NPASS * DH * DM];      // W2^T [e][n=DM][k=DH] tf32
__device__ float g_gates[T_TOKENS * NE];
__device__ int   g_tok[RPAIRS];
__device__ float g_gate[RPAIRS];
__device__ int   g_slotof[T_TOKENS * TOPK];
__device__ int   g_cnt[NE];
__device__ int   g_off[NE];
__device__ int   g_cur[NE];
__device__ int   g_tcnt[T_TOKENS];
__device__ int   g_passcnt[NPASS];
__device__ int   g_done;

// ---------------- PTX helpers (plain sm_80+ features only) ------------------
__device__ __forceinline__ uint32_t f2tf32(float x) {
    uint32_t r;
    asm("cvt.rna.tf32.f32 %0, %1;" : "=r"(r) : "f"(x));
    return r;
}
__device__ __forceinline__ uint32_t smem_u32(const void* p) {
    uint32_t r;
    asm("{ .reg .u64 t; cvta.to.shared.u64 t, %1; cvt.u32.u64 %0, t; }"
        : "=r"(r) : "l"(p));
    return r;
}
__device__ __forceinline__ void cpa16(uint32_t dst, const void* src) {
    asm volatile("cp.async.cg.shared.global [%0], [%1], 16;"
                 :: "r"(dst), "l"(src) : "memory");
}
__device__ __forceinline__ void cpa_commit() {
    asm volatile("cp.async.commit_group;" ::: "memory");
}
template <int N>
__device__ __forceinline__ void cpa_wait() {
    asm volatile("cp.async.wait_group %0;" :: "n"(N) : "memory");
}
__device__ __forceinline__ void mma_tf32(float* d, const uint32_t* a,
                                         uint32_t b0, uint32_t b1) {
    asm("mma.sync.aligned.m16n8k8.row.col.f32.tf32.tf32.f32 "
        "{%0,%1,%2,%3}, {%4,%5,%6,%7}, {%8,%9}, {%0,%1,%2,%3};"
        : "+f"(d[0]), "+f"(d[1]), "+f"(d[2]), "+f"(d[3])
        : "r"(a[0]), "r"(a[1]), "r"(a[2]), "r"(a[3]), "r"(b0), "r"(b1));
}

// ---------------- prep: weight transposes + x conversion + zeroing ----------
#define NT1 (NPASS * (DM / 32) * (DH / 32))
#define NT2 (NPASS * (DH / 32) * (DM / 32))
#define XB  ((T_TOKENS * DM) / (256 * 4))
#define ZB  (T_TOKENS / 256 + 1)

__global__ void prep_kernel(const float* __restrict__ x,
                            const float* __restrict__ rw1, const float* __restrict__ sw1,
                            const float* __restrict__ rw2, const float* __restrict__ sw2) {
    __shared__ float tile[32][33];
    const int b   = blockIdx.x;
    const int tid = threadIdx.x;
    const int tx  = tid & 31, ty = tid >> 5;

    if (b < NT1 + NT2) {
        const bool w2 = (b >= NT1);
        const int  bb = w2 ? (b - NT1) : b;
        const int  K  = w2 ? DH : DM;
        const int  N  = w2 ? DM : DH;
        const int  ntiles = N / 32;
        const int  e  = bb / ((K / 32) * ntiles);
        const int  rm = bb % ((K / 32) * ntiles);
        const int  kt = rm / ntiles, nt = rm % ntiles;
        const float* R = w2 ? rw2 : rw1;
        const float* S = w2 ? sw2 : sw1;
        const float* src = (e < NE) ? (R + (size_t)e * K * N)
                                    : (S + (size_t)(e - NE) * K * N);
        uint32_t* dst = (w2 ? g_WT2 : g_WT1) + (size_t)e * (size_t)K * N;
        const int n0 = nt * 32, k0 = kt * 32;
        #pragma unroll
        for (int i = ty; i < 32; i += 8)
            tile[i][tx] = src[(size_t)(k0 + i) * N + n0 + tx];
        __syncthreads();
        #pragma unroll
        for (int i = ty; i < 32; i += 8)
            dst[(size_t)(n0 + i) * K + k0 + tx] = f2tf32(tile[tx][i]);
    } else if (b < NT1 + NT2 + XB) {
        size_t i = ((size_t)(b - NT1 - NT2) * 256 + tid) * 4;
        float4 v = *reinterpret_cast<const float4*>(x + i);
        uint4 o;
        o.x = f2tf32(v.x); o.y = f2tf32(v.y); o.z = f2tf32(v.z); o.w = f2tf32(v.w);
        *reinterpret_cast<uint4*>(g_X + i) = o;
    } else {
        const int zb = b - NT1 - NT2 - XB;
        if (zb < T_TOKENS / 256) {
            g_tcnt[zb * 256 + tid] = 0;
        } else {
            if (tid < NE) g_cnt[tid] = 0;
            if (tid == NE) g_done = 0;
        }
    }
}

// ---------------- router (+ tail-block expert scan) --------------------------
__global__ void router_kernel(const float* __restrict__ x,
                              const float* __restrict__ rw,
                              const float* __restrict__ rb) {
    const int gw   = (blockIdx.x * blockDim.x + threadIdx.x) >> 5;
    const int lane = threadIdx.x & 31;
    {
        const float* xr = x + (size_t)gw * DM;
        float acc = __ldg(rb + lane);
        for (int k = 0; k < DM; k += 4) {
            float4 xv = *reinterpret_cast<const float4*>(xr + k);
            acc = fmaf(xv.x, __ldg(rw + (k + 0) * NE + lane), acc);
            acc = fmaf(xv.y, __ldg(rw + (k + 1) * NE + lane), acc);
            acc = fmaf(xv.z, __ldg(rw + (k + 2) * NE + lane), acc);
            acc = fmaf(xv.w, __ldg(rw + (k + 3) * NE + lane), acc);
        }
        float m = acc;
        for (int o = 16; o; o >>= 1) m = fmaxf(m, __shfl_xor_sync(0xffffffffu, m, o));
        float e = expf(acc - m);
        float s = e;
        for (int o = 16; o; o >>= 1) s += __shfl_xor_sync(0xffffffffu, s, o);
        float p = e / s;
        float pv = p, sum6 = 0.0f;
        bool sel = false;
        #pragma unroll
        for (int j = 0; j < TOPK; j++) {
            float v = pv; int idx = lane;
            for (int o = 16; o; o >>= 1) {
                float ov = __shfl_xor_sync(0xffffffffu, v, o);
                int   oi = __shfl_xor_sync(0xffffffffu, idx, o);
                if (ov > v || (ov == v && oi < idx)) { v = ov; idx = oi; }
            }
            sum6 += v;
            if (lane == idx) { pv = -1.0f; sel = true; }
        }
        float gate = sel ? (p / sum6) : 0.0f;
        g_gates[gw * NE + lane] = gate;
        if (sel) atomicAdd(&g_cnt[lane], 1);
    }
    __shared__ int s_last;
    __syncthreads();
    if (threadIdx.x == 0) {
        __threadfence();
        s_last = (atomicAdd(&g_done, 1) == (int)gridDim.x - 1) ? 1 : 0;
    }
    __syncthreads();
    if (s_last && threadIdx.x < 32) {
        const int ln = threadIdx.x;
        int c = (ln < NE) ? g_cnt[ln] : 0;
        int s = c;
        for (int o = 1; o < 32; o <<= 1) {
            int v = __shfl_up_sync(0xffffffffu, s, o);
            if (ln >= o) s += v;
        }
        if (ln < NE) { g_off[ln] = s - c; g_cur[ln] = 0; g_passcnt[ln] = c; }
        if (ln < NS) g_passcnt[NE + ln] = T_TOKENS;
    }
}

__global__ void pairs_kernel() {
    int idx = blockIdx.x * blockDim.x + threadIdx.x;
    if (idx >= T_TOKENS * NE) return;
    int t = idx >> 5, e = idx & 31;
    float gate = g_gates[idx];
    if (gate > 0.0f) {
        int pos  = atomicAdd(&g_cur[e], 1);
        int slot = g_off[e] + pos;
        g_tok[slot]  = t;
        g_gate[slot] = gate;
        int j = atomicAdd(&g_tcnt[t], 1);
        g_slotof[t * TOPK + j] = slot;
    }
}

// ---------------- expert GEMM: mma.sync tf32, 4 warps x 64x64 tiles ----------
// MODE 0: g_H = tf32(relu(gather(g_X) @ W1 + b1))   K=DM, N=DH
// MODE 1: g_O[slot] = gate * (g_H @ W2 + b2)        K=DH, N=DM
template <int MODE>
__global__ __launch_bounds__(128, 2)
void moe_gemm_tc(const float* __restrict__ RB, const float* __restrict__ SB) {
    constexpr int K   = MODE ? DH : DM;
    constexpr int N   = MODE ? DM : DH;
    constexpr int NIT = K / BK;

    const int p   = blockIdx.z;
    const int cnt = g_passcnt[p];
    const int m0  = blockIdx.y * BM;
    if (m0 >= cnt) return;
    const int n0  = blockIdx.x * BN;

    const bool routed = (p < NE);
    const int  base   = routed ? g_off[p] : (RPAIRS + (p - NE) * T_TOKENS);
    const uint32_t* WT = (MODE ? g_WT2 : g_WT1) + (size_t)p * (size_t)K * N;
    const float*    Bv = routed ? (RB + (size_t)p * N) : (SB + (size_t)(p - NE) * N);

    extern __shared__ uint8_t dsm[];
    __shared__ float s_bias[BN];

    const int tid  = threadIdx.x;      // 0..127
    const int wid  = tid >> 5;         // 0..3
    const int lane = tid & 31;

    s_bias[tid] = __ldg(Bv + n0 + tid);

    // loader: thread -> row tid (0..127), full 128B row (8 x 16B chunks)
    const uint32_t* srcA;
    if (MODE == 0) {
        int i   = m0 + tid;
        int tok = routed ? g_tok[base + (i < cnt ? i : cnt - 1)] : i;
        srcA = g_X + (size_t)tok * DM;
    } else {
        srcA = g_H + (size_t)(base + m0 + tid) * DH;
    }
    const uint32_t* srcB = WT + (size_t)(n0 + tid) * K;

    // warp / fragment coords: 2x2 warps, each 64x64
    const int wm = (wid & 1) * 64;
    const int wn = (wid >> 1) * 64;
    const int fg = lane >> 2;           // 0..7
    const int ft = lane & 3;            // 0..3

    const uint32_t sbase = smem_u32(dsm);
    uint32_t* Sm = reinterpret_cast<uint32_t*>(dsm);
    constexpr uint32_t STG = 2u * 128u * RS * 4u;   // stage bytes (A+B = 36864)

    float acc[4][8][4];
    #pragma unroll
    for (int a = 0; a < 4; a++)
        #pragma unroll
        for (int b = 0; b < 8; b++)
            #pragma unroll
            for (int c = 0; c < 4; c++) acc[a][b][c] = 0.0f;

    auto do_copy = [&](int it, int buf) {
        const int kt = it * BK;
        const uint32_t abase = sbase + (uint32_t)buf * STG;
        const uint32_t bbase = abase + 128u * RS * 4u;
        #pragma unroll
        for (int c = 0; c < 8; c++)
            cpa16(abase + (uint32_t)(tid * RS + c * 4) * 4u, srcA + kt + c * 4);
        #pragma unroll
        for (int c = 0; c < 8; c++)
            cpa16(bbase + (uint32_t)(tid * RS + c * 4) * 4u, srcB + kt + c * 4);
        cpa_commit();
    };

    do_copy(0, 0);
    #pragma unroll 1
    for (int it = 0; it < NIT; ++it) {
        const int buf = it & 1;
        if (it + 1 < NIT) { do_copy(it + 1, buf ^ 1); cpa_wait<1>(); }
        else              { cpa_wait<0>(); }
        __syncthreads();

        const uint32_t* As = Sm + (size_t)buf * (STG / 4);
        const uint32_t* Bs = As + 128 * RS;
        #pragma unroll
        for (int kk = 0; kk < 4; kk++) {
            const int k0 = kk * 8 + ft;
            const int k1 = k0 + 4;
            uint32_t af[4][4];
            #pragma unroll
            for (int mi = 0; mi < 4; mi++) {
                const int rr = wm + mi * 16 + fg;
                af[mi][0] = As[rr * RS + k0];
                af[mi][1] = As[(rr + 8) * RS + k0];
                af[mi][2] = As[rr * RS + k1];
                af[mi][3] = As[(rr + 8) * RS + k1];
            }
            #pragma unroll
            for (int nj = 0; nj < 8; nj++) {
                const int c = wn + nj * 8 + fg;
                const uint32_t b0 = Bs[c * RS + k0];
                const uint32_t b1 = Bs[c * RS + k1];
                #pragma unroll
                for (int mi = 0; mi < 4; mi++)
                    mma_tf32(acc[mi][nj], af[mi], b0, b1);
            }
        }
        __syncthreads();
    }

    // ---- epilogue
    #pragma unroll
    for (int mi = 0; mi < 4; mi++) {
        #pragma unroll
        for (int h = 0; h < 2; h++) {
            const int i = m0 + wm + mi * 16 + fg + h * 8;
            if (i >= cnt) continue;
            if (MODE == 0) {
                uint32_t* dst = g_H + (size_t)(base + i) * DH + n0;
                #pragma unroll
                for (int nj = 0; nj < 8; nj++) {
                    const int col = wn + nj * 8 + 2 * ft;
                    uint2 o;
                    o.x = f2tf32(fmaxf(acc[mi][nj][h * 2 + 0] + s_bias[col], 0.f));
                    o.y = f2tf32(fmaxf(acc[mi][nj][h * 2 + 1] + s_bias[col + 1], 0.f));
                    *reinterpret_cast<uint2*>(dst + col) = o;
                }
            } else {
                const float gate = routed ? g_gate[base + i] : (1.0f / NS);
                float* dst = g_O + (size_t)(base + i) * DM + n0;
                #pragma unroll
                for (int nj = 0; nj < 8; nj++) {
                    const int col = wn + nj * 8 + 2 * ft;
                    float2 o;
                    o.x = gate * (acc[mi][nj][h * 2 + 0] + s_bias[col]);
                    o.y = gate * (acc[mi][nj][h * 2 + 1] + s_bias[col + 1]);
                    *reinterpret_cast<float2*>(dst + col) = o;
                }
            }
        }
    }
}

// ---------------- final combine ------------------------------------------------
__global__ void combine_kernel(float* __restrict__ out) {
    const int t = blockIdx.x;
    const int c = threadIdx.x * 4;
    float4 acc = make_float4(0.f, 0.f, 0.f, 0.f);
    #pragma unroll
    for (int j = 0; j < TOPK; j++) {
        int slot = g_slotof[t * TOPK + j];
        float4 v = *reinterpret_cast<const float4*>(g_O + (size_t)slot * DM + c);
        acc.x += v.x; acc.y += v.y; acc.z += v.z; acc.w += v.w;
    }
    #pragma unroll
    for (int s = 0; s < NS; s++) {
        int slot = RPAIRS + s * T_TOKENS + t;
        float4 v = *reinterpret_cast<const float4*>(g_O + (size_t)slot * DM + c);
        acc.x += v.x; acc.y += v.y; acc.z += v.z; acc.w += v.w;
    }
    *reinterpret_cast<float4*>(out + (size_t)t * DM + c) = acc;
}

// ---------------- launch --------------------------------------------------------
extern "C" void kernel_launch(void* const* d_in, const int* in_sizes, int n_in,
                              void* d_out, int out_size) {
    const float* x        = (const float*)d_in[0];
    const float* sw1      = (const float*)d_in[1];
    const float* sb1      = (const float*)d_in[2];
    const float* sw2      = (const float*)d_in[3];
    const float* sb2      = (const float*)d_in[4];
    const float* rw1      = (const float*)d_in[5];
    const float* rb1      = (const float*)d_in[6];
    const float* rw2      = (const float*)d_in[7];
    const float* rb2      = (const float*)d_in[8];
    const float* router_w = (const float*)d_in[9];
    const float* router_b = (const float*)d_in[10];
    float* out = (float*)d_out;

    cudaFuncSetAttribute(moe_gemm_tc<0>, cudaFuncAttributeMaxDynamicSharedMemorySize, SMEM_DYN);
    cudaFuncSetAttribute(moe_gemm_tc<1>, cudaFuncAttributeMaxDynamicSharedMemorySize, SMEM_DYN);

    // launch 1: prep (transposes + x conversion + zeroing)
    prep_kernel<<<NT1 + NT2 + XB + ZB, 256>>>(x, rw1, sw1, rw2, sw2);
    // launch 2: router + fused expert scan
    router_kernel<<<(T_TOKENS * 32) / 256, 256>>>(x, router_w, router_b);
    // launch 3: pair lists
    pairs_kernel<<<(T_TOKENS * NE) / 256, 256>>>();

    // launch 4: GEMM1 (ncu profiles the 4th launch)
    dim3 g1(DH / BN, T_TOKENS / BM, NPASS);   // (11, 32, 34)
    moe_gemm_tc<0><<<g1, 128, SMEM_DYN>>>(rb1, sb1);

    // launch 5: GEMM2
    dim3 g2(DM / BN, T_TOKENS / BM, NPASS);   // (16, 32, 34)
    moe_gemm_tc<1><<<g2, 128, SMEM_DYN>>>(rb2, sb2);

    // launch 6: combine
    combine_kernel<<<T_TOKENS, 512>>>(out);
}

// round 9
// speedup vs baseline: 1.2047x; 1.0351x over previous
#include <cuda_runtime.h>
#include <cstdint>
#include <cstddef>

#define T_TOKENS 4096
#define DM 2048
#define DH 1408
#define NE 32
#define NS 2
#define TOPK 6
#define NPASS 34
#define RPAIRS (T_TOKENS * TOPK)          /* 24576 routed pairs */
#define NSLOTS (RPAIRS + NS * T_TOKENS)   /* 32768 total slots  */

#define BM 128
#define BN 128
#define BK 32
#define RS 36                              /* padded row stride (u32 words) */
#define SMEM_DYN 73728                     /* 2 stages x (A+B) x 128 x 36 x 4 */

// ---------------- scratch (static device globals; no allocations) -----------
__device__ uint32_t g_X[(size_t)T_TOKENS * DM];          // x as tf32 bits
__device__ uint32_t g_H[(size_t)NSLOTS * DH];            // hidden acts, tf32 bits
__device__ float    g_O[(size_t)NSLOTS * DM];            // per-slot outputs
__device__ uint32_t g_WT1[(size_t)NPASS * DM * DH];      // W1^T [e][n=DH][k=DM] tf32
__device__ uint32_t g_WT2[(size_t)NPASS * DH * DM];      // W2^T [e][n=DM][k=DH] tf32
__device__ float g_gates[T_TOKENS * NE];
__device__ int   g_tok[RPAIRS];
__device__ float g_gate[RPAIRS];
__device__ int   g_slotof[T_TOKENS * TOPK];
__device__ int   g_cnt[NE];
__device__ int   g_off[NE];
__device__ int   g_cur[NE];
__device__ int   g_tcnt[T_TOKENS];
__device__ int   g_passcnt[NPASS];
__device__ int   g_done;

// ---------------- PTX helpers (plain sm_80+ features only) ------------------
__device__ __forceinline__ uint32_t f2tf32(float x) {
    uint32_t r;
    asm("cvt.rna.tf32.f32 %0, %1;" : "=r"(r) : "f"(x));
    return r;
}
__device__ __forceinline__ uint32_t smem_u32(const void* p) {
    uint32_t r;
    asm("{ .reg .u64 t; cvta.to.shared.u64 t, %1; cvt.u32.u64 %0, t; }"
        : "=r"(r) : "l"(p));
    return r;
}
__device__ __forceinline__ void cpa16(uint32_t dst, const void* src) {
    asm volatile("cp.async.cg.shared.global [%0], [%1], 16;"
                 :: "r"(dst), "l"(src) : "memory");
}
__device__ __forceinline__ void cpa_commit() {
    asm volatile("cp.async.commit_group;" ::: "memory");
}
template <int N>
__device__ __forceinline__ void cpa_wait() {
    asm volatile("cp.async.wait_group %0;" :: "n"(N) : "memory");
}
__device__ __forceinline__ void mma_tf32(float* d, const uint32_t* a,
                                         uint32_t b0, uint32_t b1) {
    asm("mma.sync.aligned.m16n8k8.row.col.f32.tf32.tf32.f32 "
        "{%0,%1,%2,%3}, {%4,%5,%6,%7}, {%8,%9}, {%0,%1,%2,%3};"
        : "+f"(d[0]), "+f"(d[1]), "+f"(d[2]), "+f"(d[3])
        : "r"(a[0]), "r"(a[1]), "r"(a[2]), "r"(a[3]), "r"(b0), "r"(b1));
}
__device__ __forceinline__ void ldsm4(uint32_t& r0, uint32_t& r1,
                                      uint32_t& r2, uint32_t& r3, uint32_t a) {
    asm volatile("ldmatrix.sync.aligned.m8n8.x4.shared.b16 {%0,%1,%2,%3}, [%4];"
                 : "=r"(r0), "=r"(r1), "=r"(r2), "=r"(r3) : "r"(a));
}

// ---------------- prep: weight transposes + x conversion + zeroing ----------
#define NT1 (NPASS * (DM / 32) * (DH / 32))
#define NT2 (NPASS * (DH / 32) * (DM / 32))
#define XB  ((T_TOKENS * DM) / (256 * 4))
#define ZB  (T_TOKENS / 256 + 1)

__global__ void prep_kernel(const float* __restrict__ x,
                            const float* __restrict__ rw1, const float* __restrict__ sw1,
                            const float* __restrict__ rw2, const float* __restrict__ sw2) {
    __shared__ float tile[32][33];
    const int b   = blockIdx.x;
    const int tid = threadIdx.x;
    const int tx  = tid & 31, ty = tid >> 5;

    if (b < NT1 + NT2) {
        const bool w2 = (b >= NT1);
        const int  bb = w2 ? (b - NT1) : b;
        const int  K  = w2 ? DH : DM;
        const int  N  = w2 ? DM : DH;
        const int  ntiles = N / 32;
        const int  e  = bb / ((K / 32) * ntiles);
        const int  rm = bb % ((K / 32) * ntiles);
        const int  kt = rm / ntiles, nt = rm % ntiles;
        const float* R = w2 ? rw2 : rw1;
        const float* S = w2 ? sw2 : sw1;
        const float* src = (e < NE) ? (R + (size_t)e * K * N)
                                    : (S + (size_t)(e - NE) * K * N);
        uint32_t* dst = (w2 ? g_WT2 : g_WT1) + (size_t)e * (size_t)K * N;
        const int n0 = nt * 32, k0 = kt * 32;
        #pragma unroll
        for (int i = ty; i < 32; i += 8)
            tile[i][tx] = src[(size_t)(k0 + i) * N + n0 + tx];
        __syncthreads();
        #pragma unroll
        for (int i = ty; i < 32; i += 8)
            dst[(size_t)(n0 + i) * K + k0 + tx] = f2tf32(tile[tx][i]);
    } else if (b < NT1 + NT2 + XB) {
        size_t i = ((size_t)(b - NT1 - NT2) * 256 + tid) * 4;
        float4 v = *reinterpret_cast<const float4*>(x + i);
        uint4 o;
        o.x = f2tf32(v.x); o.y = f2tf32(v.y); o.z = f2tf32(v.z); o.w = f2tf32(v.w);
        *reinterpret_cast<uint4*>(g_X + i) = o;
    } else {
        const int zb = b - NT1 - NT2 - XB;
        if (zb < T_TOKENS / 256) {
            g_tcnt[zb * 256 + tid] = 0;
        } else {
            if (tid < NE) g_cnt[tid] = 0;
            if (tid == NE) g_done = 0;
        }
    }
}

// ---------------- router (+ tail-block expert scan) --------------------------
__global__ void router_kernel(const float* __restrict__ x,
                              const float* __restrict__ rw,
                              const float* __restrict__ rb) {
    const int gw   = (blockIdx.x * blockDim.x + threadIdx.x) >> 5;
    const int lane = threadIdx.x & 31;
    {
        const float* xr = x + (size_t)gw * DM;
        float acc = __ldg(rb + lane);
        for (int k = 0; k < DM; k += 4) {
            float4 xv = *reinterpret_cast<const float4*>(xr + k);
            acc = fmaf(xv.x, __ldg(rw + (k + 0) * NE + lane), acc);
            acc = fmaf(xv.y, __ldg(rw + (k + 1) * NE + lane), acc);
            acc = fmaf(xv.z, __ldg(rw + (k + 2) * NE + lane), acc);
            acc = fmaf(xv.w, __ldg(rw + (k + 3) * NE + lane), acc);
        }
        float m = acc;
        for (int o = 16; o; o >>= 1) m = fmaxf(m, __shfl_xor_sync(0xffffffffu, m, o));
        float e = expf(acc - m);
        float s = e;
        for (int o = 16; o; o >>= 1) s += __shfl_xor_sync(0xffffffffu, s, o);
        float p = e / s;
        float pv = p, sum6 = 0.0f;
        bool sel = false;
        #pragma unroll
        for (int j = 0; j < TOPK; j++) {
            float v = pv; int idx = lane;
            for (int o = 16; o; o >>= 1) {
                float ov = __shfl_xor_sync(0xffffffffu, v, o);
                int   oi = __shfl_xor_sync(0xffffffffu, idx, o);
                if (ov > v || (ov == v && oi < idx)) { v = ov; idx = oi; }
            }
            sum6 += v;
            if (lane == idx) { pv = -1.0f; sel = true; }
        }
        float gate = sel ? (p / sum6) : 0.0f;
        g_gates[gw * NE + lane] = gate;
        if (sel) atomicAdd(&g_cnt[lane], 1);
    }
    __shared__ int s_last;
    __syncthreads();
    if (threadIdx.x == 0) {
        __threadfence();
        s_last = (atomicAdd(&g_done, 1) == (int)gridDim.x - 1) ? 1 : 0;
    }
    __syncthreads();
    if (s_last && threadIdx.x < 32) {
        const int ln = threadIdx.x;
        int c = (ln < NE) ? g_cnt[ln] : 0;
        int s = c;
        for (int o = 1; o < 32; o <<= 1) {
            int v = __shfl_up_sync(0xffffffffu, s, o);
            if (ln >= o) s += v;
        }
        if (ln < NE) { g_off[ln] = s - c; g_cur[ln] = 0; g_passcnt[ln] = c; }
        if (ln < NS) g_passcnt[NE + ln] = T_TOKENS;
    }
}

__global__ void pairs_kernel() {
    int idx = blockIdx.x * blockDim.x + threadIdx.x;
    if (idx >= T_TOKENS * NE) return;
    int t = idx >> 5, e = idx & 31;
    float gate = g_gates[idx];
    if (gate > 0.0f) {
        int pos  = atomicAdd(&g_cur[e], 1);
        int slot = g_off[e] + pos;
        g_tok[slot]  = t;
        g_gate[slot] = gate;
        int j = atomicAdd(&g_tcnt[t], 1);
        g_slotof[t * TOPK + j] = slot;
    }
}

// ---------------- expert GEMM: mma.sync tf32 + ldmatrix, 8 warps x 32x64 -----
// MODE 0: g_H = tf32(relu(gather(g_X) @ W1 + b1))   K=DM, N=DH
// MODE 1: g_O[slot] = gate * (g_H @ W2 + b2)        K=DH, N=DM
template <int MODE>
__global__ __launch_bounds__(256, 2)
void moe_gemm_tc(const float* __restrict__ RB, const float* __restrict__ SB) {
    constexpr int K   = MODE ? DH : DM;
    constexpr int N   = MODE ? DM : DH;
    constexpr int NIT = K / BK;

    const int p   = blockIdx.z;
    const int cnt = g_passcnt[p];
    const int m0  = blockIdx.y * BM;
    if (m0 >= cnt) return;
    const int n0  = blockIdx.x * BN;

    const bool routed = (p < NE);
    const int  base   = routed ? g_off[p] : (RPAIRS + (p - NE) * T_TOKENS);
    const uint32_t* WT = (MODE ? g_WT2 : g_WT1) + (size_t)p * (size_t)K * N;
    const float*    Bv = routed ? (RB + (size_t)p * N) : (SB + (size_t)(p - NE) * N);

    extern __shared__ uint8_t dsm[];
    __shared__ float s_bias[BN];

    const int tid  = threadIdx.x;      // 0..255
    const int wid  = tid >> 5;         // 0..7
    const int lane = tid & 31;

    if (tid < BN) s_bias[tid] = __ldg(Bv + n0 + tid);

    // loader: thread -> row r (0..127), 4 chunks of 16B at cb..cb+3
    const int r  = tid & 127;
    const int cb = (tid >> 7) * 4;
    const uint32_t* srcA;
    if (MODE == 0) {
        int i   = m0 + r;
        int tok = routed ? g_tok[base + (i < cnt ? i : cnt - 1)] : i;
        srcA = g_X + (size_t)tok * DM;
    } else {
        srcA = g_H + (size_t)(base + m0 + r) * DH;
    }
    const uint32_t* srcB = WT + (size_t)(n0 + r) * K;

    // warp / fragment coords: 4 warps along M (32 rows), 2 along N (64 cols)
    const int wm = (wid & 3) * 32;
    const int wn = (wid >> 2) * 64;
    const int fg = lane >> 2;           // 0..7
    const int ft = lane & 3;            // 0..3

    const uint32_t sbase = smem_u32(dsm);
    constexpr uint32_t STG    = 2u * 128u * RS * 4u;   // stage bytes (36864)
    constexpr uint32_t B_BYTE = 128u * RS * 4u;        // B offset inside stage

    // ldmatrix lane-constant byte offsets (within A / B region of a stage)
    // A tile mi: matrices {rows 0-7 k0-3, rows 8-15 k0-3, rows 0-7 k4-7, rows 8-15 k4-7}
    const uint32_t a_off = (uint32_t)(((wm + (lane & 15)) * RS + ((lane >> 4) << 2)) << 2);
    // B tile pair njp: {n0-7 k0-3, n0-7 k4-7, n8-15 k0-3, n8-15 k4-7}
    const uint32_t b_off = (uint32_t)(((wn + (lane & 7) + ((lane >> 4) << 3)) * RS
                                       + (((lane >> 3) & 1) << 2)) << 2);

    float acc[2][8][4];
    #pragma unroll
    for (int a = 0; a < 2; a++)
        #pragma unroll
        for (int b = 0; b < 8; b++)
            #pragma unroll
            for (int c = 0; c < 4; c++) acc[a][b][c] = 0.0f;

    auto do_copy = [&](int it, int buf) {
        const int kt = it * BK;
        const uint32_t abase = sbase + (uint32_t)buf * STG;
        const uint32_t bbase = abase + B_BYTE;
        #pragma unroll
        for (int c = 0; c < 4; c++)
            cpa16(abase + (uint32_t)(r * RS + (cb + c) * 4) * 4u,
                  srcA + kt + (cb + c) * 4);
        #pragma unroll
        for (int c = 0; c < 4; c++)
            cpa16(bbase + (uint32_t)(r * RS + (cb + c) * 4) * 4u,
                  srcB + kt + (cb + c) * 4);
        cpa_commit();
    };

    do_copy(0, 0);
    #pragma unroll 1
    for (int it = 0; it < NIT; ++it) {
        const int buf = it & 1;
        if (it + 1 < NIT) { do_copy(it + 1, buf ^ 1); cpa_wait<1>(); }
        else              { cpa_wait<0>(); }
        __syncthreads();

        const uint32_t a_sm = sbase + (uint32_t)buf * STG + a_off;
        const uint32_t b_sm = sbase + (uint32_t)buf * STG + B_BYTE + b_off;
        #pragma unroll
        for (int kk = 0; kk < 4; kk++) {
            const uint32_t kb = (uint32_t)kk * 32u;   // 8 words * 4B
            uint32_t af[2][4];
            ldsm4(af[0][0], af[0][1], af[0][2], af[0][3], a_sm + kb);
            ldsm4(af[1][0], af[1][1], af[1][2], af[1][3],
                  a_sm + kb + 16u * RS * 4u);
            #pragma unroll
            for (int njp = 0; njp < 4; njp++) {
                uint32_t b00, b01, b10, b11;   // {b0(nj), b1(nj), b0(nj+1), b1(nj+1)}
                ldsm4(b00, b01, b10, b11, b_sm + kb + (uint32_t)njp * (16u * RS * 4u));
                mma_tf32(acc[0][njp * 2 + 0], af[0], b00, b01);
                mma_tf32(acc[1][njp * 2 + 0], af[1], b00, b01);
                mma_tf32(acc[0][njp * 2 + 1], af[0], b10, b11);
                mma_tf32(acc[1][njp * 2 + 1], af[1], b10, b11);
            }
        }
        __syncthreads();
    }

    // ---- epilogue
    #pragma unroll
    for (int mi = 0; mi < 2; mi++) {
        #pragma unroll
        for (int h = 0; h < 2; h++) {
            const int i = m0 + wm + mi * 16 + fg + h * 8;
            if (i >= cnt) continue;
            if (MODE == 0) {
                uint32_t* dst = g_H + (size_t)(base + i) * DH + n0;
                #pragma unroll
                for (int nj = 0; nj < 8; nj++) {
                    const int col = wn + nj * 8 + 2 * ft;
                    uint2 o;
                    o.x = f2tf32(fmaxf(acc[mi][nj][h * 2 + 0] + s_bias[col], 0.f));
                    o.y = f2tf32(fmaxf(acc[mi][nj][h * 2 + 1] + s_bias[col + 1], 0.f));
                    *reinterpret_cast<uint2*>(dst + col) = o;
                }
            } else {
                const float gate = routed ? g_gate[base + i] : (1.0f / NS);
                float* dst = g_O + (size_t)(base + i) * DM + n0;
                #pragma unroll
                for (int nj = 0; nj < 8; nj++) {
                    const int col = wn + nj * 8 + 2 * ft;
                    float2 o;
                    o.x = gate * (acc[mi][nj][h * 2 + 0] + s_bias[col]);
                    o.y = gate * (acc[mi][nj][h * 2 + 1] + s_bias[col + 1]);
                    *reinterpret_cast<float2*>(dst + col) = o;
                }
            }
        }
    }
}

// ---------------- final combine ------------------------------------------------
__global__ void combine_kernel(float* __restrict__ out) {
    const int t = blockIdx.x;
    const int c = threadIdx.x * 4;
    float4 acc = make_float4(0.f, 0.f, 0.f, 0.f);
    #pragma unroll
    for (int j = 0; j < TOPK; j++) {
        int slot = g_slotof[t * TOPK + j];
        float4 v = *reinterpret_cast<const float4*>(g_O + (size_t)slot * DM + c);
        acc.x += v.x; acc.y += v.y; acc.z += v.z; acc.w += v.w;
    }
    #pragma unroll
    for (int s = 0; s < NS; s++) {
        int slot = RPAIRS + s * T_TOKENS + t;
        float4 v = *reinterpret_cast<const float4*>(g_O + (size_t)slot * DM + c);
        acc.x += v.x; acc.y += v.y; acc.z += v.z; acc.w += v.w;
    }
    *reinterpret_cast<float4*>(out + (size_t)t * DM + c) = acc;
}

// ---------------- launch --------------------------------------------------------
extern "C" void kernel_launch(void* const* d_in, const int* in_sizes, int n_in,
                              void* d_out, int out_size) {
    const float* x        = (const float*)d_in[0];
    const float* sw1      = (const float*)d_in[1];
    const float* sb1      = (const float*)d_in[2];
    const float* sw2      = (const float*)d_in[3];
    const float* sb2      = (const float*)d_in[4];
    const float* rw1      = (const float*)d_in[5];
    const float* rb1      = (const float*)d_in[6];
    const float* rw2      = (const float*)d_in[7];
    const float* rb2      = (const float*)d_in[8];
    const float* router_w = (const float*)d_in[9];
    const float* router_b = (const float*)d_in[10];
    float* out = (float*)d_out;

    cudaFuncSetAttribute(moe_gemm_tc<0>, cudaFuncAttributeMaxDynamicSharedMemorySize, SMEM_DYN);
    cudaFuncSetAttribute(moe_gemm_tc<1>, cudaFuncAttributeMaxDynamicSharedMemorySize, SMEM_DYN);

    // launch 1: prep (transposes + x conversion + zeroing)
    prep_kernel<<<NT1 + NT2 + XB + ZB, 256>>>(x, rw1, sw1, rw2, sw2);
    // launch 2: router + fused expert scan
    router_kernel<<<(T_TOKENS * 32) / 256, 256>>>(x, router_w, router_b);
    // launch 3: pair lists
    pairs_kernel<<<(T_TOKENS * NE) / 256, 256>>>();

    // launch 4: GEMM1 (ncu profiles the 4th launch)
    dim3 g1(DH / BN, T_TOKENS / BM, NPASS);   // (11, 32, 34)
    moe_gemm_tc<0><<<g1, 256, SMEM_DYN>>>(rb1, sb1);

    // launch 5: GEMM2
    dim3 g2(DM / BN, T_TOKENS / BM, NPASS);   // (16, 32, 34)
    moe_gemm_tc<1><<<g2, 256, SMEM_DYN>>>(rb2, sb2);

    // launch 6: combine
    combine_kernel<<<T_TOKENS, 512>>>(out);
}